// round 15
// baseline (speedup 1.0000x reference)
#include <cuda_runtime.h>
#include <cuda_bf16.h>
#include <math.h>
#include <stdint.h>
#include <mma.h>

using namespace nvcuda;

#define NIMG 4
#define CIN 512
#define HW 4096
#define NANCH 36864   /* 64*64*9 */
#define PRE 6000
#define POST 300
#define KTOT 4608     /* 512*9 */
#define NCH16 288     /* 4608/16 */
#define TS 24         /* bf16 tile row stride in elements (16 + 8 pad) */
#define TILEELT (128 * TS)                 /* elements per tile */
#define STAGEELT (6 * TILEELT)             /* A1,A2,A3,B1,B2,B3 */
#define DYNSMEM (2 * STAGEELT * 2)         /* bytes: 73728 */

/* output layout (float32, concatenated in reference return order) */
#define OFF_LOCS   0
#define OFF_SCORES 589824
#define OFF_ROIS   884736
#define OFF_RIDX   889536
#define OFF_ANCH   890736

__device__ float    g_mid[NIMG * CIN * HW];
__device__ float4   g_boxes[NIMG * NANCH];
__device__ unsigned g_keys[NIMG * NANCH];
__device__ int      g_cand[NIMG * PRE];
__device__ int      g_nvalid[NIMG];

__device__ __forceinline__ unsigned fkey(float f) {
    unsigned b = __float_as_uint(f);
    return (b & 0x80000000u) ? ~b : (b | 0x80000000u);
}

/* split x into 3 bf16 slices: x = s1 + s2 + s3 (exact to ~2^-24 rel) */
__device__ __forceinline__ void bsplit(float x, __nv_bfloat16& s1,
                                       __nv_bfloat16& s2, __nv_bfloat16& s3) {
    s1 = __float2bfloat16(x);
    float r1 = x - __bfloat162float(s1);
    s2 = __float2bfloat16(r1);
    float r2 = r1 - __bfloat162float(s2);
    s3 = __float2bfloat16(r2);
}

/* ============================================================
 * 3x3 conv: implicit GEMM on tensor cores via bf16 8-product split
 * (drops only a3*b3 ~ 2^-32), with PER-CHUNK accumulator promotion
 * to CUDA-core fp32 (short TC chains -> kills biased TC-accumulate
 * truncation error).
 * CTA 128(co) x 128(px), 8 warps (64x32 tile), BK=16, double buffer.
 * ============================================================ */
__global__ __launch_bounds__(256, 1)
void conv3x3_bf16(const float* __restrict__ in, const float* __restrict__ Wc,
                  const float* __restrict__ bc)
{
    extern __shared__ __nv_bfloat16 smb[];

    const int t    = threadIdx.x;
    const int wid  = t >> 5;
    const int n    = blockIdx.z;
    const int co0  = blockIdx.y * 128;
    const int p0   = blockIdx.x * 128;

    const int wm = wid >> 2;     /* 0..1: warp row (64 co) */
    const int wn = wid & 3;      /* 0..3: warp col (32 px) */

    /* producer: thread -> (row, k-half of 8) for both tiles */
    const int prow = t >> 1;
    const int half = t & 1;
    const float* inN  = in + (size_t)n * CIN * HW;
    const float* Arow = Wc + (size_t)(co0 + prow) * KTOT + half * 8;
    const int p = p0 + prow, py = p >> 6, pxx = p & 63;

    /* master accumulators, promoted in fp32 on CUDA cores */
    float master[4][2][8];
#pragma unroll
    for (int i = 0; i < 4; i++)
#pragma unroll
        for (int j = 0; j < 2; j++)
#pragma unroll
            for (int e = 0; e < 8; e++) master[i][j][e] = 0.f;

    float pa[8], pb[8];

    auto fetch = [&](int c) {
        const int k0 = c * 16;
        *(float4*)&pa[0] = *(const float4*)(Arow + k0);
        *(float4*)&pa[4] = *(const float4*)(Arow + k0 + 4);
#pragma unroll
        for (int e = 0; e < 8; e++) {
            int kk = k0 + half * 8 + e;
            int ci = kk / 9;
            int r  = kk - ci * 9;
            int ry = r / 3, rx = r - ry * 3;
            int y = py + ry - 1, x = pxx + rx - 1;
            pb[e] = ((unsigned)y < 64u && (unsigned)x < 64u)
                      ? __ldg(inN + (size_t)ci * HW + (y << 6) + x) : 0.f;
        }
    };
    auto store = [&](int stage) {
        __nv_bfloat16* st = smb + stage * STAGEELT;
        __nv_bfloat16 h1[8], h2[8], h3[8];
#pragma unroll
        for (int e = 0; e < 8; e++) bsplit(pa[e], h1[e], h2[e], h3[e]);
        int base = prow * TS + half * 8;
        *(uint4*)&st[0 * TILEELT + base] = *(uint4*)h1;
        *(uint4*)&st[1 * TILEELT + base] = *(uint4*)h2;
        *(uint4*)&st[2 * TILEELT + base] = *(uint4*)h3;
#pragma unroll
        for (int e = 0; e < 8; e++) bsplit(pb[e], h1[e], h2[e], h3[e]);
        *(uint4*)&st[3 * TILEELT + base] = *(uint4*)h1;
        *(uint4*)&st[4 * TILEELT + base] = *(uint4*)h2;
        *(uint4*)&st[5 * TILEELT + base] = *(uint4*)h3;
    };

    /* ---- chunk 0 ---- */
    fetch(0);
    store(0);
    __syncthreads();

    /* ---- main loop ---- */
    for (int c = 0; c < NCH16; c++) {
        if (c + 1 < NCH16) fetch(c + 1);

        {
            const __nv_bfloat16* st = smb + (c & 1) * STAGEELT;
            const __nv_bfloat16* A1 = st + 0 * TILEELT;
            const __nv_bfloat16* A2 = st + 1 * TILEELT;
            const __nv_bfloat16* A3 = st + 2 * TILEELT;
            const __nv_bfloat16* B1 = st + 3 * TILEELT;
            const __nv_bfloat16* B2 = st + 4 * TILEELT;
            const __nv_bfloat16* B3 = st + 5 * TILEELT;

            wmma::fragment<wmma::matrix_b, 16, 16, 16, __nv_bfloat16, wmma::col_major> b1[2], b2[2], b3[2];
#pragma unroll
            for (int j = 0; j < 2; j++) {
                int off = (wn * 32 + j * 16) * TS;
                wmma::load_matrix_sync(b1[j], B1 + off, TS);
                wmma::load_matrix_sync(b2[j], B2 + off, TS);
                wmma::load_matrix_sync(b3[j], B3 + off, TS);
            }
#pragma unroll
            for (int i = 0; i < 4; i++) {
                wmma::fragment<wmma::matrix_a, 16, 16, 16, __nv_bfloat16, wmma::row_major> a1, a2, a3;
                int off = (wm * 64 + i * 16) * TS;
                wmma::load_matrix_sync(a1, A1 + off, TS);
                wmma::load_matrix_sync(a2, A2 + off, TS);
                wmma::load_matrix_sync(a3, A3 + off, TS);
#pragma unroll
                for (int j = 0; j < 2; j++) {
                    /* fresh accumulator per chunk -> short TC chain */
                    wmma::fragment<wmma::accumulator, 16, 16, 16, float> tmp;
                    wmma::fill_fragment(tmp, 0.0f);
                    /* 8 of 9 split products (only a3*b3 ~2^-32 dropped) */
                    wmma::mma_sync(tmp, a1, b1[j], tmp);
                    wmma::mma_sync(tmp, a1, b2[j], tmp);
                    wmma::mma_sync(tmp, a2, b1[j], tmp);
                    wmma::mma_sync(tmp, a1, b3[j], tmp);
                    wmma::mma_sync(tmp, a3, b1[j], tmp);
                    wmma::mma_sync(tmp, a2, b2[j], tmp);
                    wmma::mma_sync(tmp, a2, b3[j], tmp);
                    wmma::mma_sync(tmp, a3, b2[j], tmp);
                    /* promote to fp32 master on CUDA cores (RN adds) */
#pragma unroll
                    for (int e = 0; e < 8; e++) master[i][j][e] += tmp.x[e];
                }
            }
        }

        if (c + 1 < NCH16) {
            store((c + 1) & 1);
            __syncthreads();
        }
    }
    __syncthreads();

    /* ---- epilogue: master -> smem staging -> bias+relu -> g_mid ---- */
    {
        float* stag = (float*)smb;   /* [128][132] = 67584 B < DYNSMEM */
        wmma::fragment<wmma::accumulator, 16, 16, 16, float> outf;
#pragma unroll
        for (int i = 0; i < 4; i++)
#pragma unroll
            for (int j = 0; j < 2; j++) {
#pragma unroll
                for (int e = 0; e < 8; e++) outf.x[e] = master[i][j][e];
                wmma::store_matrix_sync(stag + (wm * 64 + i * 16) * 132 + wn * 32 + j * 16,
                                        outf, 132, wmma::mem_row_major);
            }
        __syncthreads();

        int row  = t >> 1;
        int hh   = t & 1;
        float bvv = bc[co0 + row];
        float* dst = g_mid + (size_t)n * CIN * HW + (size_t)(co0 + row) * HW + p0 + hh * 64;
        const float* srcr = stag + row * 132 + hh * 64;
#pragma unroll
        for (int j = 0; j < 16; j++) {
            float4 v = *(const float4*)(srcr + j * 4);
            v.x = fmaxf(v.x + bvv, 0.f);
            v.y = fmaxf(v.y + bvv, 0.f);
            v.z = fmaxf(v.z + bvv, 0.f);
            v.w = fmaxf(v.w + bvv, 0.f);
            *(float4*)(dst + j * 4) = v;
        }
    }
}

/* ============================================================
 * 1x1 convs (score 18ch + loc 36ch) -> rpn_locs / rpn_scores
 * ============================================================ */
__global__ __launch_bounds__(256)
void conv1x1_kernel(const float* __restrict__ Ws, const float* __restrict__ bs,
                    const float* __restrict__ Wl, const float* __restrict__ bl,
                    float* __restrict__ out)
{
    __shared__ float sm[16][64];
    const int t  = threadIdx.x;
    const int n  = blockIdx.y;
    const int p0 = blockIdx.x * 64;
    const int co = t & 63;
    const int pg = t >> 6;
    const bool active = co < 54;

    const float* mid  = g_mid + (size_t)n * CIN * HW;
    const float* wrow = (co < 18) ? (Ws + co * CIN) : (Wl + (co - 18) * CIN);

    float acc[16];
#pragma unroll
    for (int i = 0; i < 16; i++) acc[i] = 0.f;

    for (int k0 = 0; k0 < CIN; k0 += 16) {
        int l  = t * 4;
        int kk = l >> 6;
        int pp = l & 63;
        *(float4*)&sm[kk][pp] = *(const float4*)(mid + (size_t)(k0 + kk) * HW + p0 + pp);
        __syncthreads();
        if (active) {
#pragma unroll
            for (int k = 0; k < 16; k++) {
                float wv = __ldg(wrow + k0 + k);
#pragma unroll
                for (int pq = 0; pq < 16; pq++) acc[pq] += wv * sm[k][pg * 16 + pq];
            }
        }
        __syncthreads();
    }

    if (active) {
        float bvv = (co < 18) ? bs[co] : bl[co - 18];
#pragma unroll
        for (int pq = 0; pq < 16; pq++) {
            int px = p0 + pg * 16 + pq;
            float v = acc[pq] + bvv;
            if (co < 18) {
                int a = co >> 1, cc = co & 1;
                out[OFF_SCORES + (((size_t)n * NANCH + (size_t)px * 9 + a) * 2 + cc)] = v;
            } else {
                int lidx = co - 18;
                int a = lidx >> 2, cc = lidx & 3;
                out[OFF_LOCS + (((size_t)n * NANCH + (size_t)px * 9 + a) * 4 + cc)] = v;
            }
        }
    }
}

/* ============================================================
 * decode: anchors, loc2bbox, clip, min-size filter, softmax fg
 * ============================================================ */
__global__ void decode_kernel(float* __restrict__ out,
                              const int* __restrict__ p_ih, const int* __restrict__ p_iw)
{
    int i = blockIdx.x * blockDim.x + threadIdx.x;
    if (i >= NIMG * NANCH) return;
    int n   = i / NANCH;
    int j   = i - n * NANCH;
    int pos = j / 9;
    int a   = j - pos * 9;
    int y   = pos >> 6;
    int x   = pos & 63;

    int ri = a / 3, si = a - ri * 3;
    double rr  = (ri == 0) ? 0.5 : ((ri == 1) ? 1.0 : 2.0);
    double ssc = (si == 0) ? 8.0 : ((si == 1) ? 16.0 : 32.0);
    double hh = 16.0 * ssc * sqrt(rr);
    double wd = 16.0 * ssc * sqrt(1.0 / rr);
    float sy = (float)(y * 16);
    float sx = (float)(x * 16);
    float ay0 = (float)(8.0 - hh * 0.5) + sy;
    float ax0 = (float)(8.0 - wd * 0.5) + sx;
    float ay1 = (float)(8.0 + hh * 0.5) + sy;
    float ax1 = (float)(8.0 + wd * 0.5) + sx;

    if (n == 0) {
        out[OFF_ANCH + (size_t)j * 4 + 0] = ay0;
        out[OFF_ANCH + (size_t)j * 4 + 1] = ax0;
        out[OFF_ANCH + (size_t)j * 4 + 2] = ay1;
        out[OFF_ANCH + (size_t)j * 4 + 3] = ax1;
    }

    const float* lp = out + OFF_LOCS + ((size_t)n * NANCH + j) * 4;
    float dy = lp[0], dx = lp[1], dh = lp[2], dw = lp[3];

    float ah = ay1 - ay0, aw = ax1 - ax0;
    float cy = ay0 + 0.5f * ah, cx = ax0 + 0.5f * aw;
    float ncy = dy * ah + cy;
    float ncx = dx * aw + cx;
    float nh  = expf(dh) * ah;
    float nw  = expf(dw) * aw;

    int ihv = p_ih[0], iwv = p_iw[0];
    float fh = (ihv > 262144) ? __int_as_float(ihv) : (float)ihv;
    float fw = (iwv > 262144) ? __int_as_float(iwv) : (float)iwv;

    float y0 = fminf(fmaxf(ncy - 0.5f * nh, 0.f), fh);
    float x0 = fminf(fmaxf(ncx - 0.5f * nw, 0.f), fw);
    float y1 = fminf(fmaxf(ncy + 0.5f * nh, 0.f), fh);
    float x1 = fminf(fmaxf(ncx + 0.5f * nw, 0.f), fw);

    bool ok = ((y1 - y0) >= 16.0f) && ((x1 - x0) >= 16.0f);

    const float* sp = out + OFF_SCORES + ((size_t)n * NANCH + j) * 2;
    float s0 = sp[0], s1 = sp[1];
    float m  = fmaxf(s0, s1);
    float e0 = expf(s0 - m), e1 = expf(s1 - m);
    float fg = e1 / (e0 + e1);

    float sc = ok ? fg : -1e10f;
    g_boxes[i] = make_float4(y0, x0, y1, x1);
    g_keys[i]  = fkey(sc);
}

/* ============================================================
 * per-image top-6000 radix select + bitonic sort (desc, tie by idx)
 * ============================================================ */
__global__ __launch_bounds__(1024)
void select_kernel()
{
    extern __shared__ unsigned long long list[]; /* 8192 entries */
    __shared__ int hist[256];
    __shared__ unsigned sh_prefix, sh_prefmask;
    __shared__ int sh_K, sh_cnt, sh_eqbase;
    __shared__ int s_warpEq[32];

    const int n   = blockIdx.x;
    const int tid = threadIdx.x;
    const unsigned* keys = g_keys + (size_t)n * NANCH;

    if (tid == 0) { sh_prefix = 0; sh_prefmask = 0; sh_K = PRE; sh_cnt = 0; sh_eqbase = 0; }
    __syncthreads();

    for (int byte = 3; byte >= 0; byte--) {
        for (int b = tid; b < 256; b += 1024) hist[b] = 0;
        __syncthreads();
        unsigned pf = sh_prefix, pm = sh_prefmask;
        for (int i = tid; i < NANCH; i += 1024) {
            unsigned u = keys[i];
            if ((u & pm) == pf) atomicAdd(&hist[(u >> (byte * 8)) & 255], 1);
        }
        __syncthreads();
        if (tid == 0) {
            int K = sh_K, cum = 0, b = 255;
            for (; b > 0; b--) {
                if (cum + hist[b] >= K) break;
                cum += hist[b];
            }
            sh_prefix  |= ((unsigned)b) << (byte * 8);
            sh_prefmask |= 0xFFu << (byte * 8);
            sh_K = K - cum;
        }
        __syncthreads();
    }
    const unsigned T = sh_prefix;
    const int needEq = sh_K;

    const int wid = tid >> 5, lane = tid & 31;
    for (int base = 0; base < NANCH; base += 1024) {
        int i = base + tid;
        unsigned u = keys[i];
        bool above = (u > T);
        bool eq    = (u == T);
        unsigned mask = __ballot_sync(0xFFFFFFFFu, eq);
        if (lane == 0) s_warpEq[wid] = __popc(mask);
        if (above) {
            int pq = atomicAdd(&sh_cnt, 1);
            list[pq] = ((unsigned long long)u << 32) | (unsigned)(~(unsigned)i);
        }
        __syncthreads();
        if (eq) {
            int pre = 0;
            for (int w2 = 0; w2 < wid; w2++) pre += s_warpEq[w2];
            int rank = sh_eqbase + pre + __popc(mask & ((1u << lane) - 1u));
            if (rank < needEq) {
                int pq = atomicAdd(&sh_cnt, 1);
                list[pq] = ((unsigned long long)u << 32) | (unsigned)(~(unsigned)i);
            }
        }
        __syncthreads();
        if (tid == 0) {
            int tot = 0;
            for (int w2 = 0; w2 < 32; w2++) tot += s_warpEq[w2];
            sh_eqbase += tot;
        }
        __syncthreads();
    }

    for (int r = PRE + tid; r < 8192; r += 1024) list[r] = 0ull;
    __syncthreads();

    for (int k = 2; k <= 8192; k <<= 1)
        for (int j = k >> 1; j > 0; j >>= 1) {
            for (int i = tid; i < 8192; i += 1024) {
                int ixj = i ^ j;
                if (ixj > i) {
                    unsigned long long A = list[i], B = list[ixj];
                    if (((i & k) == 0) ? (A < B) : (A > B)) { list[i] = B; list[ixj] = A; }
                }
            }
            __syncthreads();
        }

    const unsigned negk = fkey(-1e10f);
    for (int r = tid; r < PRE; r += 1024) {
        unsigned long long v = list[r];
        unsigned key = (unsigned)(v >> 32);
        int idx = (int)(~(unsigned)v);
        g_cand[n * PRE + r] = idx;
        bool valid = key > negk;
        if (valid) {
            unsigned nk2 = (r < PRE - 1) ? (unsigned)(list[r + 1] >> 32) : 0u;
            if (r == PRE - 1 || nk2 <= negk) g_nvalid[n] = r + 1;
        } else if (r == 0) {
            g_nvalid[n] = 0;
        }
    }
}

/* ============================================================
 * greedy NMS (== reference scan semantics), one block per image
 * ============================================================ */
__global__ __launch_bounds__(1024)
void nms_kernel(float* __restrict__ out)
{
    extern __shared__ unsigned char smraw[];
    float4* sbox = (float4*)smraw;
    unsigned char* supp = (unsigned char*)(sbox + PRE);
    int* keep = (int*)(smraw + PRE * 16 + 6400);
    __shared__ int s_cur, s_nk, s_pick, s_done;

    const int n   = blockIdx.x;
    const int tid = threadIdx.x;

    for (int r = tid; r < PRE; r += 1024) {
        int idx = g_cand[n * PRE + r];
        sbox[r] = g_boxes[(size_t)n * NANCH + idx];
        supp[r] = 0;
    }
    if (tid == 0) { s_cur = 0; s_nk = 0; }
    const int limit = g_nvalid[n];
    __syncthreads();

    while (true) {
        if (tid == 0) {
            int c = s_cur;
            while (c < limit && supp[c]) c++;
            if (c >= limit || s_nk >= POST) {
                s_done = 1;
            } else {
                s_done = 0;
                s_pick = c;
                keep[s_nk] = c;
                s_nk = s_nk + 1;
                s_cur = c + 1;
            }
        }
        __syncthreads();
        if (s_done) break;

        float4 bb = sbox[s_pick];
        float a1 = (bb.z - bb.x) * (bb.w - bb.y);
        for (int j = s_pick + 1 + tid; j < PRE; j += 1024) {
            if (supp[j]) continue;
            float4 cb = sbox[j];
            float ty = fmaxf(bb.x, cb.x);
            float tx = fmaxf(bb.y, cb.y);
            float by = fminf(bb.z, cb.z);
            float bx = fminf(bb.w, cb.w);
            float inter = fmaxf(by - ty, 0.f) * fmaxf(bx - tx, 0.f);
            float a2 = (cb.z - cb.x) * (cb.w - cb.y);
            float iou = inter / (a1 + a2 - inter + 1e-9f);
            if (iou > 0.7f) supp[j] = 1;
        }
        __syncthreads();
    }

    const int nk = s_nk;
    for (int k2 = tid; k2 < POST; k2 += 1024) {
        float4 b = make_float4(0.f, 0.f, 0.f, 0.f);
        if (k2 < nk) b = sbox[keep[k2]];
        size_t o = OFF_ROIS + ((size_t)n * POST + k2) * 4;
        out[o + 0] = b.x;
        out[o + 1] = b.y;
        out[o + 2] = b.z;
        out[o + 3] = b.w;
        out[OFF_RIDX + (size_t)n * POST + k2] = (float)n;
    }
}

extern "C" void kernel_launch(void* const* d_in, const int* in_sizes, int n_in,
                              void* d_out, int out_size)
{
    const float* base_feat = (const float*)d_in[0];
    const float* Wc  = (const float*)d_in[1];
    const float* bc  = (const float*)d_in[2];
    const float* Wsc = (const float*)d_in[3];
    const float* bsc = (const float*)d_in[4];
    const float* Wl  = (const float*)d_in[5];
    const float* bl  = (const float*)d_in[6];
    const int*   ih  = (const int*)d_in[7];
    const int*   iw  = (const int*)d_in[8];
    float* out = (float*)d_out;

    (void)in_sizes; (void)n_in; (void)out_size;

    cudaFuncSetAttribute(conv3x3_bf16, cudaFuncAttributeMaxDynamicSharedMemorySize, DYNSMEM);
    cudaFuncSetAttribute(select_kernel, cudaFuncAttributeMaxDynamicSharedMemorySize, 65536);
    cudaFuncSetAttribute(nms_kernel, cudaFuncAttributeMaxDynamicSharedMemorySize, 110592);

    conv3x3_bf16<<<dim3(32, 4, NIMG), 256, DYNSMEM>>>(base_feat, Wc, bc);
    conv1x1_kernel<<<dim3(64, NIMG), 256>>>(Wsc, bsc, Wl, bl, out);
    decode_kernel<<<(NIMG * NANCH + 255) / 256, 256>>>(out, ih, iw);
    select_kernel<<<NIMG, 1024, 65536>>>();
    nms_kernel<<<NIMG, 1024, 110592>>>(out);
}

// round 17
// speedup vs baseline: 1.8914x; 1.8914x over previous
#include <cuda_runtime.h>
#include <math.h>
#include <stdint.h>

#define NIMG 4
#define CIN 512
#define COUT 512
#define HW 4096
#define NANCH 36864   /* 64*64*9 */
#define PRE 6000
#define POST 300
#define NTILE 1024    /* 32x32 tiles of 2x2 per image */
#define NTOT 4096     /* NIMG * NTILE */
#define USTRIDE (COUT * CIN)        /* 262144 per pos */
#define VSTRIDE (CIN * NTOT)        /* 2097152 per pos */
#define MSTRIDE (COUT * NTOT)       /* 2097152 per pos */

/* output layout (float32, concatenated in reference return order) */
#define OFF_LOCS   0
#define OFF_SCORES 589824
#define OFF_ROIS   884736
#define OFF_RIDX   889536
#define OFF_ANCH   890736

__device__ float    g_U[16 * USTRIDE];     /* 16.8 MB  transformed weights */
__device__ float    g_V[16 * VSTRIDE];     /* 134 MB   transformed inputs  */
__device__ float    g_M[16 * MSTRIDE];     /* 134 MB   GEMM results        */
__device__ float    g_mid[NIMG * COUT * HW];
__device__ float4   g_boxes[NIMG * NANCH];
__device__ unsigned g_keys[NIMG * NANCH];
__device__ int      g_cand[NIMG * PRE];
__device__ int      g_nvalid[NIMG];

__device__ __forceinline__ unsigned fkey(float f) {
    unsigned b = __float_as_uint(f);
    return (b & 0x80000000u) ? ~b : (b | 0x80000000u);
}

/* ============================================================
 * Stage 0: weight transform  U = G g G^T  (per co,ci)
 * G = [[1,0,0],[.5,.5,.5],[.5,-.5,.5],[0,0,1]]
 * ============================================================ */
__global__ __launch_bounds__(256)
void wtrans_kernel(const float* __restrict__ Wc)
{
    int idx = blockIdx.x * 256 + threadIdx.x;
    if (idx >= COUT * CIN) return;
    int co = idx >> 9;
    int ci = idx & 511;
    const float* g = Wc + (size_t)co * (CIN * 9) + ci * 9;
    float g0, g1, g2, t[4][3];
#pragma unroll
    for (int c = 0; c < 3; c++) {
        g0 = g[0 * 3 + c]; g1 = g[1 * 3 + c]; g2 = g[2 * 3 + c];
        t[0][c] = g0;
        t[1][c] = 0.5f * (g0 + g1 + g2);
        t[2][c] = 0.5f * (g0 - g1 + g2);
        t[3][c] = g2;
    }
    float* u = g_U + (size_t)co * CIN + ci;
#pragma unroll
    for (int r = 0; r < 4; r++) {
        float a0 = t[r][0], a1 = t[r][1], a2 = t[r][2];
        u[(r * 4 + 0) * (size_t)USTRIDE] = a0;
        u[(r * 4 + 1) * (size_t)USTRIDE] = 0.5f * (a0 + a1 + a2);
        u[(r * 4 + 2) * (size_t)USTRIDE] = 0.5f * (a0 - a1 + a2);
        u[(r * 4 + 3) * (size_t)USTRIDE] = a2;
    }
}

/* ============================================================
 * Stage 1: input transform  V = B^T d B  (per img,ci,tile)
 * B^T = [[1,0,-1,0],[0,1,1,0],[0,-1,1,0],[0,1,0,-1]]
 * ============================================================ */
__global__ __launch_bounds__(256)
void itrans_kernel(const float* __restrict__ in)
{
    int idx = blockIdx.x * 256 + threadIdx.x;
    if (idx >= NIMG * CIN * NTILE) return;
    int tile = idx & 1023;
    int ci   = (idx >> 10) & 511;
    int img  = idx >> 19;
    int ty = tile >> 5, tx = tile & 31;
    int y0 = 2 * ty - 1, x0 = 2 * tx - 1;

    const float* src = in + ((size_t)img * CIN + ci) * HW;
    float d[4][4];
#pragma unroll
    for (int r = 0; r < 4; r++) {
        int y = y0 + r;
#pragma unroll
        for (int c = 0; c < 4; c++) {
            int x = x0 + c;
            d[r][c] = ((unsigned)y < 64u && (unsigned)x < 64u) ? src[(y << 6) + x] : 0.f;
        }
    }
    float t[4][4];
#pragma unroll
    for (int c = 0; c < 4; c++) {
        t[0][c] = d[0][c] - d[2][c];
        t[1][c] = d[1][c] + d[2][c];
        t[2][c] = d[2][c] - d[1][c];
        t[3][c] = d[1][c] - d[3][c];
    }
    float* v = g_V + (size_t)ci * NTOT + img * NTILE + tile;
#pragma unroll
    for (int r = 0; r < 4; r++) {
        float a0 = t[r][0], a1 = t[r][1], a2 = t[r][2], a3 = t[r][3];
        v[(r * 4 + 0) * (size_t)VSTRIDE] = a0 - a2;
        v[(r * 4 + 1) * (size_t)VSTRIDE] = a1 + a2;
        v[(r * 4 + 2) * (size_t)VSTRIDE] = a2 - a1;
        v[(r * 4 + 3) * (size_t)VSTRIDE] = a1 - a3;
    }
}

/* ============================================================
 * Stage 2: 16 batched SGEMMs  M[pos] = U[pos](512x512) x V[pos](512x4096)
 * BM=128, BN=128, BK=8, 256 threads, 8x8/thread (R2 ceiling structure).
 * ============================================================ */
__global__ __launch_bounds__(256, 2)
void gemm16_kernel()
{
    __shared__ float As[8][128];
    __shared__ float Bs[8][128];

    const int t    = threadIdx.x;
    const int pos  = blockIdx.z;
    const int co0  = blockIdx.y * 128;
    const int n0   = blockIdx.x * 128;

    const int am = t >> 1;
    const int ak = (t & 1) * 4;
    const int bk = t >> 5;
    const int bn = (t & 31) * 4;
    const int tx = t & 15;
    const int ty = t >> 4;

    const float* Arow = g_U + (size_t)pos * USTRIDE + (size_t)(co0 + am) * CIN + ak;
    const float* Vb   = g_V + (size_t)pos * VSTRIDE;

    float acc[8][8];
#pragma unroll
    for (int i = 0; i < 8; i++)
#pragma unroll
        for (int j = 0; j < 8; j++) acc[i][j] = 0.f;

    for (int k0 = 0; k0 < CIN; k0 += 8) {
        float4 a4 = *(const float4*)(Arow + k0);
        As[ak + 0][am] = a4.x;
        As[ak + 1][am] = a4.y;
        As[ak + 2][am] = a4.z;
        As[ak + 3][am] = a4.w;
        *(float4*)&Bs[bk][bn] = *(const float4*)(Vb + (size_t)(k0 + bk) * NTOT + n0 + bn);
        __syncthreads();

#pragma unroll
        for (int k = 0; k < 8; k++) {
            float a[8], b[8];
            *(float4*)(a)     = *(const float4*)&As[k][ty * 8];
            *(float4*)(a + 4) = *(const float4*)&As[k][ty * 8 + 4];
            *(float4*)(b)     = *(const float4*)&Bs[k][tx * 8];
            *(float4*)(b + 4) = *(const float4*)&Bs[k][tx * 8 + 4];
#pragma unroll
            for (int i = 0; i < 8; i++)
#pragma unroll
                for (int j = 0; j < 8; j++) acc[i][j] += a[i] * b[j];
        }
        __syncthreads();
    }

    float* Mp = g_M + (size_t)pos * MSTRIDE;
#pragma unroll
    for (int i = 0; i < 8; i++) {
        int co = co0 + ty * 8 + i;
        float* dst = Mp + (size_t)co * NTOT + n0 + tx * 8;
        *(float4*)(dst)     = *(float4*)&acc[i][0];
        *(float4*)(dst + 4) = *(float4*)&acc[i][4];
    }
}

/* ============================================================
 * Stage 3: output transform  Y = A^T M A + bias, relu -> g_mid
 * A^T = [[1,1,1,0],[0,1,-1,-1]]
 * ============================================================ */
__global__ __launch_bounds__(256)
void otrans_kernel(const float* __restrict__ bc)
{
    int idx = blockIdx.x * 256 + threadIdx.x;
    if (idx >= NIMG * COUT * NTILE) return;
    int tile = idx & 1023;
    int co   = (idx >> 10) & 511;
    int img  = idx >> 19;
    int ty = tile >> 5, tx = tile & 31;

    const float* m = g_M + (size_t)co * NTOT + img * NTILE + tile;
    float mm[16];
#pragma unroll
    for (int p2 = 0; p2 < 16; p2++) mm[p2] = m[(size_t)p2 * MSTRIDE];

    float s[2][4];
#pragma unroll
    for (int c = 0; c < 4; c++) {
        s[0][c] = mm[0 * 4 + c] + mm[1 * 4 + c] + mm[2 * 4 + c];
        s[1][c] = mm[1 * 4 + c] - mm[2 * 4 + c] - mm[3 * 4 + c];
    }
    float bv = bc[co];
    float y00 = s[0][0] + s[0][1] + s[0][2] + bv;
    float y01 = s[0][1] - s[0][2] - s[0][3] + bv;
    float y10 = s[1][0] + s[1][1] + s[1][2] + bv;
    float y11 = s[1][1] - s[1][2] - s[1][3] + bv;

    float* dst = g_mid + ((size_t)img * COUT + co) * HW + (2 * ty) * 64 + 2 * tx;
    dst[0]  = fmaxf(y00, 0.f);
    dst[1]  = fmaxf(y01, 0.f);
    dst[64] = fmaxf(y10, 0.f);
    dst[65] = fmaxf(y11, 0.f);
}

/* ============================================================
 * 1x1 convs (score 18ch + loc 36ch) -> rpn_locs / rpn_scores
 * ============================================================ */
__global__ __launch_bounds__(256)
void conv1x1_kernel(const float* __restrict__ Ws, const float* __restrict__ bs,
                    const float* __restrict__ Wl, const float* __restrict__ bl,
                    float* __restrict__ out)
{
    __shared__ float sm[16][64];
    const int t  = threadIdx.x;
    const int n  = blockIdx.y;
    const int p0 = blockIdx.x * 64;
    const int co = t & 63;
    const int pg = t >> 6;
    const bool active = co < 54;

    const float* mid  = g_mid + (size_t)n * CIN * HW;
    const float* wrow = (co < 18) ? (Ws + co * CIN) : (Wl + (co - 18) * CIN);

    float acc[16];
#pragma unroll
    for (int i = 0; i < 16; i++) acc[i] = 0.f;

    for (int k0 = 0; k0 < CIN; k0 += 16) {
        int l  = t * 4;
        int kk = l >> 6;
        int pp = l & 63;
        *(float4*)&sm[kk][pp] = *(const float4*)(mid + (size_t)(k0 + kk) * HW + p0 + pp);
        __syncthreads();
        if (active) {
#pragma unroll
            for (int k = 0; k < 16; k++) {
                float wv = __ldg(wrow + k0 + k);
#pragma unroll
                for (int pq = 0; pq < 16; pq++) acc[pq] += wv * sm[k][pg * 16 + pq];
            }
        }
        __syncthreads();
    }

    if (active) {
        float bvv = (co < 18) ? bs[co] : bl[co - 18];
#pragma unroll
        for (int pq = 0; pq < 16; pq++) {
            int px = p0 + pg * 16 + pq;
            float v = acc[pq] + bvv;
            if (co < 18) {
                int a = co >> 1, cc = co & 1;
                out[OFF_SCORES + (((size_t)n * NANCH + (size_t)px * 9 + a) * 2 + cc)] = v;
            } else {
                int lidx = co - 18;
                int a = lidx >> 2, cc = lidx & 3;
                out[OFF_LOCS + (((size_t)n * NANCH + (size_t)px * 9 + a) * 4 + cc)] = v;
            }
        }
    }
}

/* ============================================================
 * decode: anchors, loc2bbox, clip, min-size filter, softmax fg
 * ============================================================ */
__global__ void decode_kernel(float* __restrict__ out,
                              const int* __restrict__ p_ih, const int* __restrict__ p_iw)
{
    int i = blockIdx.x * blockDim.x + threadIdx.x;
    if (i >= NIMG * NANCH) return;
    int n   = i / NANCH;
    int j   = i - n * NANCH;
    int pos = j / 9;
    int a   = j - pos * 9;
    int y   = pos >> 6;
    int x   = pos & 63;

    int ri = a / 3, si = a - ri * 3;
    double rr  = (ri == 0) ? 0.5 : ((ri == 1) ? 1.0 : 2.0);
    double ssc = (si == 0) ? 8.0 : ((si == 1) ? 16.0 : 32.0);
    double hh = 16.0 * ssc * sqrt(rr);
    double wd = 16.0 * ssc * sqrt(1.0 / rr);
    float sy = (float)(y * 16);
    float sx = (float)(x * 16);
    float ay0 = (float)(8.0 - hh * 0.5) + sy;
    float ax0 = (float)(8.0 - wd * 0.5) + sx;
    float ay1 = (float)(8.0 + hh * 0.5) + sy;
    float ax1 = (float)(8.0 + wd * 0.5) + sx;

    if (n == 0) {
        out[OFF_ANCH + (size_t)j * 4 + 0] = ay0;
        out[OFF_ANCH + (size_t)j * 4 + 1] = ax0;
        out[OFF_ANCH + (size_t)j * 4 + 2] = ay1;
        out[OFF_ANCH + (size_t)j * 4 + 3] = ax1;
    }

    const float* lp = out + OFF_LOCS + ((size_t)n * NANCH + j) * 4;
    float dy = lp[0], dx = lp[1], dh = lp[2], dw = lp[3];

    float ah = ay1 - ay0, aw = ax1 - ax0;
    float cy = ay0 + 0.5f * ah, cx = ax0 + 0.5f * aw;
    float ncy = dy * ah + cy;
    float ncx = dx * aw + cx;
    float nh  = expf(dh) * ah;
    float nw  = expf(dw) * aw;

    int ihv = p_ih[0], iwv = p_iw[0];
    float fh = (ihv > 262144) ? __int_as_float(ihv) : (float)ihv;
    float fw = (iwv > 262144) ? __int_as_float(iwv) : (float)iwv;

    float y0 = fminf(fmaxf(ncy - 0.5f * nh, 0.f), fh);
    float x0 = fminf(fmaxf(ncx - 0.5f * nw, 0.f), fw);
    float y1 = fminf(fmaxf(ncy + 0.5f * nh, 0.f), fh);
    float x1 = fminf(fmaxf(ncx + 0.5f * nw, 0.f), fw);

    bool ok = ((y1 - y0) >= 16.0f) && ((x1 - x0) >= 16.0f);

    const float* sp = out + OFF_SCORES + ((size_t)n * NANCH + j) * 2;
    float s0 = sp[0], s1 = sp[1];
    float m  = fmaxf(s0, s1);
    float e0 = expf(s0 - m), e1 = expf(s1 - m);
    float fg = e1 / (e0 + e1);

    float sc = ok ? fg : -1e10f;
    g_boxes[i] = make_float4(y0, x0, y1, x1);
    g_keys[i]  = fkey(sc);
}

/* ============================================================
 * per-image top-6000 radix select + bitonic sort (desc, tie by idx)
 * ============================================================ */
__global__ __launch_bounds__(1024)
void select_kernel()
{
    extern __shared__ unsigned long long list[]; /* 8192 entries */
    __shared__ int hist[256];
    __shared__ unsigned sh_prefix, sh_prefmask;
    __shared__ int sh_K, sh_cnt, sh_eqbase;
    __shared__ int s_warpEq[32];

    const int n   = blockIdx.x;
    const int tid = threadIdx.x;
    const unsigned* keys = g_keys + (size_t)n * NANCH;

    if (tid == 0) { sh_prefix = 0; sh_prefmask = 0; sh_K = PRE; sh_cnt = 0; sh_eqbase = 0; }
    __syncthreads();

    for (int byte = 3; byte >= 0; byte--) {
        for (int b = tid; b < 256; b += 1024) hist[b] = 0;
        __syncthreads();
        unsigned pf = sh_prefix, pm = sh_prefmask;
        for (int i = tid; i < NANCH; i += 1024) {
            unsigned u = keys[i];
            if ((u & pm) == pf) atomicAdd(&hist[(u >> (byte * 8)) & 255], 1);
        }
        __syncthreads();
        if (tid == 0) {
            int K = sh_K, cum = 0, b = 255;
            for (; b > 0; b--) {
                if (cum + hist[b] >= K) break;
                cum += hist[b];
            }
            sh_prefix  |= ((unsigned)b) << (byte * 8);
            sh_prefmask |= 0xFFu << (byte * 8);
            sh_K = K - cum;
        }
        __syncthreads();
    }
    const unsigned T = sh_prefix;
    const int needEq = sh_K;

    const int wid = tid >> 5, lane = tid & 31;
    for (int base = 0; base < NANCH; base += 1024) {
        int i = base + tid;
        unsigned u = keys[i];
        bool above = (u > T);
        bool eq    = (u == T);
        unsigned mask = __ballot_sync(0xFFFFFFFFu, eq);
        if (lane == 0) s_warpEq[wid] = __popc(mask);
        if (above) {
            int pq = atomicAdd(&sh_cnt, 1);
            list[pq] = ((unsigned long long)u << 32) | (unsigned)(~(unsigned)i);
        }
        __syncthreads();
        if (eq) {
            int pre = 0;
            for (int w2 = 0; w2 < wid; w2++) pre += s_warpEq[w2];
            int rank = sh_eqbase + pre + __popc(mask & ((1u << lane) - 1u));
            if (rank < needEq) {
                int pq = atomicAdd(&sh_cnt, 1);
                list[pq] = ((unsigned long long)u << 32) | (unsigned)(~(unsigned)i);
            }
        }
        __syncthreads();
        if (tid == 0) {
            int tot = 0;
            for (int w2 = 0; w2 < 32; w2++) tot += s_warpEq[w2];
            sh_eqbase += tot;
        }
        __syncthreads();
    }

    for (int r = PRE + tid; r < 8192; r += 1024) list[r] = 0ull;
    __syncthreads();

    for (int k = 2; k <= 8192; k <<= 1)
        for (int j = k >> 1; j > 0; j >>= 1) {
            for (int i = tid; i < 8192; i += 1024) {
                int ixj = i ^ j;
                if (ixj > i) {
                    unsigned long long A = list[i], B = list[ixj];
                    if (((i & k) == 0) ? (A < B) : (A > B)) { list[i] = B; list[ixj] = A; }
                }
            }
            __syncthreads();
        }

    const unsigned negk = fkey(-1e10f);
    for (int r = tid; r < PRE; r += 1024) {
        unsigned long long v = list[r];
        unsigned key = (unsigned)(v >> 32);
        int idx = (int)(~(unsigned)v);
        g_cand[n * PRE + r] = idx;
        bool valid = key > negk;
        if (valid) {
            unsigned nk2 = (r < PRE - 1) ? (unsigned)(list[r + 1] >> 32) : 0u;
            if (r == PRE - 1 || nk2 <= negk) g_nvalid[n] = r + 1;
        } else if (r == 0) {
            g_nvalid[n] = 0;
        }
    }
}

/* ============================================================
 * greedy NMS (== reference scan semantics), one block per image
 * ============================================================ */
__global__ __launch_bounds__(1024)
void nms_kernel(float* __restrict__ out)
{
    extern __shared__ unsigned char smraw[];
    float4* sbox = (float4*)smraw;
    unsigned char* supp = (unsigned char*)(sbox + PRE);
    int* keep = (int*)(smraw + PRE * 16 + 6400);
    __shared__ int s_cur, s_nk, s_pick, s_done;

    const int n   = blockIdx.x;
    const int tid = threadIdx.x;

    for (int r = tid; r < PRE; r += 1024) {
        int idx = g_cand[n * PRE + r];
        sbox[r] = g_boxes[(size_t)n * NANCH + idx];
        supp[r] = 0;
    }
    if (tid == 0) { s_cur = 0; s_nk = 0; }
    const int limit = g_nvalid[n];
    __syncthreads();

    while (true) {
        if (tid == 0) {
            int c = s_cur;
            while (c < limit && supp[c]) c++;
            if (c >= limit || s_nk >= POST) {
                s_done = 1;
            } else {
                s_done = 0;
                s_pick = c;
                keep[s_nk] = c;
                s_nk = s_nk + 1;
                s_cur = c + 1;
            }
        }
        __syncthreads();
        if (s_done) break;

        float4 bb = sbox[s_pick];
        float a1 = (bb.z - bb.x) * (bb.w - bb.y);
        for (int j = s_pick + 1 + tid; j < PRE; j += 1024) {
            if (supp[j]) continue;
            float4 cb = sbox[j];
            float ty = fmaxf(bb.x, cb.x);
            float tx = fmaxf(bb.y, cb.y);
            float by = fminf(bb.z, cb.z);
            float bx = fminf(bb.w, cb.w);
            float inter = fmaxf(by - ty, 0.f) * fmaxf(bx - tx, 0.f);
            float a2 = (cb.z - cb.x) * (cb.w - cb.y);
            float iou = inter / (a1 + a2 - inter + 1e-9f);
            if (iou > 0.7f) supp[j] = 1;
        }
        __syncthreads();
    }

    const int nk = s_nk;
    for (int k2 = tid; k2 < POST; k2 += 1024) {
        float4 b = make_float4(0.f, 0.f, 0.f, 0.f);
        if (k2 < nk) b = sbox[keep[k2]];
        size_t o = OFF_ROIS + ((size_t)n * POST + k2) * 4;
        out[o + 0] = b.x;
        out[o + 1] = b.y;
        out[o + 2] = b.z;
        out[o + 3] = b.w;
        out[OFF_RIDX + (size_t)n * POST + k2] = (float)n;
    }
}

extern "C" void kernel_launch(void* const* d_in, const int* in_sizes, int n_in,
                              void* d_out, int out_size)
{
    const float* base_feat = (const float*)d_in[0];
    const float* Wc  = (const float*)d_in[1];
    const float* bc  = (const float*)d_in[2];
    const float* Wsc = (const float*)d_in[3];
    const float* bsc = (const float*)d_in[4];
    const float* Wl  = (const float*)d_in[5];
    const float* bl  = (const float*)d_in[6];
    const int*   ih  = (const int*)d_in[7];
    const int*   iw  = (const int*)d_in[8];
    float* out = (float*)d_out;

    (void)in_sizes; (void)n_in; (void)out_size;

    cudaFuncSetAttribute(select_kernel, cudaFuncAttributeMaxDynamicSharedMemorySize, 65536);
    cudaFuncSetAttribute(nms_kernel, cudaFuncAttributeMaxDynamicSharedMemorySize, 110592);

    wtrans_kernel<<<(COUT * CIN + 255) / 256, 256>>>(Wc);
    itrans_kernel<<<(NIMG * CIN * NTILE + 255) / 256, 256>>>(base_feat);
    gemm16_kernel<<<dim3(32, 4, 16), 256>>>();
    otrans_kernel<<<(NIMG * COUT * NTILE + 255) / 256, 256>>>(bc);
    conv1x1_kernel<<<dim3(64, NIMG), 256>>>(Wsc, bsc, Wl, bl, out);
    decode_kernel<<<(NIMG * NANCH + 255) / 256, 256>>>(out, ih, iw);
    select_kernel<<<NIMG, 1024, 65536>>>();
    nms_kernel<<<NIMG, 1024, 110592>>>(out);
}